// round 10
// baseline (speedup 1.0000x reference)
#include <cuda_runtime.h>
#include <cuda_fp16.h>
#include <cstdint>

// ---------------- problem shape ----------------
#define Bn 4
#define Hn 16
#define Sn 2048
#define Dn 64
#define BHn (Bn*Hn)
#define MQ 128            // queries per CTA
#define TN 128            // keys per smem tile
#define NTILES (Sn/TN)    // 16
#define NT 128            // threads, 4 warps; each warp owns 2 m-blocks

// ---------------- smem layout (bytes) ----------------
#define SM_QH   0
#define SM_KH   16384
#define SM_VH   32768
#define SM_BIAS 49152     // 2048 floats: 0 or -1e30
#define SM_RS   57344
#define SM_INV  57856
#define SM_STAGE 58368    // 64 rows x 68 floats (272B, conflict-free pad)
#define RSTR    68
#define SMEM_BYTES (SM_STAGE + 64*272)   // 75776 ; x3 CTAs = 227328B <= smem/SM

__device__ __forceinline__ uint32_t swz(uint32_t o) { return o ^ ((o >> 3) & 0x70); }

__device__ __forceinline__ uint32_t s2u(const void* p) {
    uint32_t a;
    asm("{ .reg .u64 t; cvta.to.shared.u64 t, %1; cvt.u32.u64 %0, t; }" : "=r"(a) : "l"(p));
    return a;
}
__device__ __forceinline__ uint32_t ph2(float a, float b) {
    __half2 h = __floats2half2_rn(a, b);
    return *reinterpret_cast<uint32_t*>(&h);
}
__device__ __forceinline__ void ldsm4(uint32_t* r, uint32_t a) {
    asm volatile("ldmatrix.sync.aligned.m8n8.x4.shared.b16 {%0,%1,%2,%3}, [%4];"
        : "=r"(r[0]), "=r"(r[1]), "=r"(r[2]), "=r"(r[3]) : "r"(a));
}
__device__ __forceinline__ void ldsm4t(uint32_t* r, uint32_t a) {
    asm volatile("ldmatrix.sync.aligned.m8n8.x4.trans.shared.b16 {%0,%1,%2,%3}, [%4];"
        : "=r"(r[0]), "=r"(r[1]), "=r"(r[2]), "=r"(r[3]) : "r"(a));
}
__device__ __forceinline__ void mma16816(float* d, const uint32_t* a, const uint32_t* b) {
    asm volatile("mma.sync.aligned.m16n8k16.row.col.f32.f16.f16.f32 "
        "{%0,%1,%2,%3},{%4,%5,%6,%7},{%8,%9},{%0,%1,%2,%3};"
        : "+f"(d[0]), "+f"(d[1]), "+f"(d[2]), "+f"(d[3])
        : "r"(a[0]), "r"(a[1]), "r"(a[2]), "r"(a[3]), "r"(b[0]), "r"(b[1]));
}

// 128x64 fp32 tile -> fp16 smem, swizzled 128B rows. NT=128 -> 8 iters.
__device__ __forceinline__ void load_tile_h(const float* __restrict__ g, char* hi, int tid) {
    #pragma unroll
    for (int it = 0; it < 8; ++it) {
        int chunk = tid + it * NT;
        int r = chunk >> 3, c8 = chunk & 7;
        const float4* p = (const float4*)(g + r * Dn + c8 * 8);
        float4 f0 = p[0], f1 = p[1];
        uint4 hv;
        hv.x = ph2(f0.x, f0.y); hv.y = ph2(f0.z, f0.w);
        hv.z = ph2(f1.x, f1.y); hv.w = ph2(f1.z, f1.w);
        *(uint4*)(hi + swz((uint32_t)(r * 128 + c8 * 16))) = hv;
    }
}

__global__ __launch_bounds__(NT, 3)
void attn_hmma(const float* __restrict__ Q, const float* __restrict__ K,
               const float* __restrict__ V, const int* __restrict__ Mk,
               float* __restrict__ Out, float* __restrict__ Attn)
{
    extern __shared__ char smem[];
    const uint32_t su = s2u(smem);
    const int tid = threadIdx.x, w = tid >> 5, lane = tid & 31;
    const int bh = blockIdx.y, b = bh >> 4;
    const int q0 = blockIdx.x * MQ;
    const size_t qbase = ((size_t)bh * Sn + q0) * Dn;

    // mask -> float bias in smem (0 or -1e30)
    float* bias = (float*)(smem + SM_BIAS);
    #pragma unroll
    for (int i = 0; i < Sn / NT; ++i) {
        int idx = tid + i * NT;
        bias[idx] = Mk[(size_t)b * Sn + idx] ? 0.f : -1e30f;
    }

    // Q tile -> smem (persists across both passes)
    load_tile_h(Q + qbase, smem + SM_QH, tid);
    __syncthreads();

    // per-mb "virtual warp" row: mb=0 -> w, mb=1 -> w+4
    const uint32_t qcs = ((lane >> 4) & 1) * 16;
    const int krb = (lane & 7) + ((lane >> 4) & 1) * 8;
    const uint32_t kcs = ((lane >> 3) & 1) * 16;
    const int cb0 = (lane & 3) * 2;
    int qr[2];
    qr[0] = w * 16 + (lane & 7) + ((lane >> 3) & 1) * 8;
    qr[1] = qr[0] + 64;

    // ============ Pass 1: row sums; Q frags hoisted, K shared over mb ============
    {
        uint32_t qf[2][4][4];
        #pragma unroll
        for (int mb = 0; mb < 2; ++mb)
            #pragma unroll
            for (int ks = 0; ks < 4; ++ks)
                ldsm4(qf[mb][ks], su + SM_QH + swz((uint32_t)(qr[mb] * 128 + ks * 32) + qcs));

        float rs[2][2] = {{0.f, 0.f}, {0.f, 0.f}};
        for (int t = 0; t < NTILES; ++t) {
            if (t) __syncthreads();
            load_tile_h(K + ((size_t)bh * Sn + t * TN) * Dn, smem + SM_KH, tid);
            __syncthreads();
            #pragma unroll
            for (int c = 0; c < 2; ++c) {
                float c_[2][8][4];
                #pragma unroll
                for (int mb = 0; mb < 2; ++mb)
                    #pragma unroll
                    for (int nt = 0; nt < 8; ++nt)
                        #pragma unroll
                        for (int i = 0; i < 4; ++i) c_[mb][nt][i] = 0.f;
                #pragma unroll
                for (int ks = 0; ks < 4; ++ks) {
                    #pragma unroll
                    for (int pr = 0; pr < 4; ++pr) {
                        uint32_t bh_[4];
                        ldsm4(bh_, su + SM_KH + swz((uint32_t)((c * 64 + pr * 16 + krb) * 128 + ks * 32) + kcs));
                        #pragma unroll
                        for (int mb = 0; mb < 2; ++mb) {
                            mma16816(c_[mb][2 * pr],     qf[mb][ks], bh_);
                            mma16816(c_[mb][2 * pr + 1], qf[mb][ks], bh_ + 2);
                        }
                    }
                }
                const float* bp = bias + t * TN + c * 64 + cb0;
                #pragma unroll
                for (int nt = 0; nt < 8; ++nt) {
                    float2 bb = *(const float2*)(bp + nt * 8);
                    #pragma unroll
                    for (int mb = 0; mb < 2; ++mb) {
                        rs[mb][0] += __expf(fmaf(c_[mb][nt][0], 0.125f, bb.x)) + __expf(fmaf(c_[mb][nt][1], 0.125f, bb.y));
                        rs[mb][1] += __expf(fmaf(c_[mb][nt][2], 0.125f, bb.x)) + __expf(fmaf(c_[mb][nt][3], 0.125f, bb.y));
                    }
                }
            }
        }
        #pragma unroll
        for (int mb = 0; mb < 2; ++mb)
            #pragma unroll
            for (int h = 0; h < 2; ++h) {
                rs[mb][h] += __shfl_xor_sync(~0u, rs[mb][h], 1);
                rs[mb][h] += __shfl_xor_sync(~0u, rs[mb][h], 2);
            }
        float* rsm = (float*)(smem + SM_RS);
        if ((lane & 3) == 0) {
            #pragma unroll
            for (int mb = 0; mb < 2; ++mb) {
                int r = (w + 4 * mb) * 16 + (lane >> 2);
                rsm[r]     = rs[mb][0];
                rsm[r + 8] = rs[mb][1];
            }
        }
    }
    __syncthreads();
    {
        float* rsm = (float*)(smem + SM_RS);
        float* invm = (float*)(smem + SM_INV);
        invm[tid] = 1.0f / rsm[tid];
    }
    __syncthreads();
    float inv_[2][2];
    {
        const float* invm = (const float*)(smem + SM_INV);
        #pragma unroll
        for (int mb = 0; mb < 2; ++mb) {
            inv_[mb][0] = invm[(w + 4 * mb) * 16 + (lane >> 2)];
            inv_[mb][1] = invm[(w + 4 * mb) * 16 + 8 + (lane >> 2)];
        }
    }

    // ============ Pass 2: QK, staged attn write via cp.async.bulk, PV ============
    float O[2][8][4];
    #pragma unroll
    for (int mb = 0; mb < 2; ++mb)
        #pragma unroll
        for (int j = 0; j < 8; ++j)
            #pragma unroll
            for (int i = 0; i < 4; ++i) O[mb][j][i] = 0.f;

    const int vrb = (lane & 7) + ((lane >> 3) & 1) * 8;
    const uint32_t vcs = ((lane >> 4) & 1) * 16;
    float* stg = (float*)(smem + SM_STAGE);
    const int lr0 = w * 16 + (lane >> 2);      // staging row for half 0
    float* const attn_base = Attn + ((size_t)bh * Sn) * Sn;

    for (int t = 0; t < NTILES; ++t) {
        __syncthreads();
        load_tile_h(K + ((size_t)bh * Sn + t * TN) * Dn, smem + SM_KH, tid);
        load_tile_h(V + ((size_t)bh * Sn + t * TN) * Dn, smem + SM_VH, tid);
        __syncthreads();
        #pragma unroll
        for (int c = 0; c < 2; ++c) {
            float c_[2][8][4];
            #pragma unroll
            for (int mb = 0; mb < 2; ++mb)
                #pragma unroll
                for (int nt = 0; nt < 8; ++nt)
                    #pragma unroll
                    for (int i = 0; i < 4; ++i) c_[mb][nt][i] = 0.f;
            #pragma unroll
            for (int ks = 0; ks < 4; ++ks) {
                uint32_t ah[2][4];
                #pragma unroll
                for (int mb = 0; mb < 2; ++mb)
                    ldsm4(ah[mb], su + SM_QH + swz((uint32_t)(qr[mb] * 128 + ks * 32) + qcs));
                #pragma unroll
                for (int pr = 0; pr < 4; ++pr) {
                    uint32_t bh_[4];
                    ldsm4(bh_, su + SM_KH + swz((uint32_t)((c * 64 + pr * 16 + krb) * 128 + ks * 32) + kcs));
                    #pragma unroll
                    for (int mb = 0; mb < 2; ++mb) {
                        mma16816(c_[mb][2 * pr],     ah[mb], bh_);
                        mma16816(c_[mb][2 * pr + 1], ah[mb], bh_ + 2);
                    }
                }
            }
            // epilogue: per mb, stage P into smem then bulk-copy 64 rows to global
            uint32_t PH[2][8][2];
            const float* bp = bias + t * TN + c * 64 + cb0;
            #pragma unroll
            for (int mb = 0; mb < 2; ++mb) {
                // release staging buffer (wait for previous round's smem reads)
                asm volatile("cp.async.bulk.wait_group.read 0;" ::: "memory");
                __syncthreads();
                #pragma unroll
                for (int nt = 0; nt < 8; ++nt) {
                    int colc = nt * 8 + cb0;
                    float2 bb = *(const float2*)(bp + nt * 8);
                    float p0 = __expf(fmaf(c_[mb][nt][0], 0.125f, bb.x)) * inv_[mb][0];
                    float p1 = __expf(fmaf(c_[mb][nt][1], 0.125f, bb.y)) * inv_[mb][0];
                    float p2 = __expf(fmaf(c_[mb][nt][2], 0.125f, bb.x)) * inv_[mb][1];
                    float p3 = __expf(fmaf(c_[mb][nt][3], 0.125f, bb.y)) * inv_[mb][1];
                    *(float2*)&stg[lr0 * RSTR + colc]       = make_float2(p0, p1);
                    *(float2*)&stg[(lr0 + 8) * RSTR + colc] = make_float2(p2, p3);
                    PH[mb][nt][0] = ph2(p0, p1);
                    PH[mb][nt][1] = ph2(p2, p3);
                }
                asm volatile("fence.proxy.async.shared::cta;" ::: "memory");
                __syncthreads();
                if (tid < 64) {
                    float* dst = attn_base + ((size_t)(q0 + 64 * mb + tid)) * Sn + t * TN + c * 64;
                    uint32_t src = su + SM_STAGE + (uint32_t)tid * (RSTR * 4);
                    asm volatile("cp.async.bulk.global.shared::cta.bulk_group [%0], [%1], 256;"
                                 :: "l"(dst), "r"(src) : "memory");
                    asm volatile("cp.async.bulk.commit_group;" ::: "memory");
                }
            }
            // PV: V fragments loaded once, consumed by both m-blocks
            #pragma unroll
            for (int kp = 0; kp < 4; ++kp) {
                uint32_t pah[2][4];
                #pragma unroll
                for (int mb = 0; mb < 2; ++mb) {
                    pah[mb][0] = PH[mb][2*kp][0];   pah[mb][1] = PH[mb][2*kp][1];
                    pah[mb][2] = PH[mb][2*kp+1][0]; pah[mb][3] = PH[mb][2*kp+1][1];
                }
                int vrow = c * 64 + kp * 16 + vrb;
                #pragma unroll
                for (int dp = 0; dp < 4; ++dp) {
                    uint32_t vo = swz((uint32_t)(vrow * 128 + dp * 32) + vcs);
                    uint32_t vb[4];
                    ldsm4t(vb, su + SM_VH + vo);
                    #pragma unroll
                    for (int mb = 0; mb < 2; ++mb) {
                        mma16816(O[mb][2 * dp],     pah[mb], vb);
                        mma16816(O[mb][2 * dp + 1], pah[mb], vb + 2);
                    }
                }
            }
        }
    }

    // drain all outstanding bulk copies (write completion)
    asm volatile("cp.async.bulk.wait_group 0;" ::: "memory");

    // ============ O writeback ============
    #pragma unroll
    for (int mb = 0; mb < 2; ++mb) {
        float* orow0 = Out + ((size_t)bh * Sn + q0 + (w + 4 * mb) * 16 + (lane >> 2)) * Dn;
        float* orow1 = orow0 + 8 * Dn;
        #pragma unroll
        for (int dt = 0; dt < 8; ++dt) {
            int col = dt * 8 + cb0;
            *(float2*)(orow0 + col) = make_float2(O[mb][dt][0], O[mb][dt][1]);
            *(float2*)(orow1 + col) = make_float2(O[mb][dt][2], O[mb][dt][3]);
        }
    }
}

extern "C" void kernel_launch(void* const* d_in, const int* in_sizes, int n_in,
                              void* d_out, int out_size)
{
    const float* Q    = (const float*)d_in[0];
    const float* K    = (const float*)d_in[1];
    const float* V    = (const float*)d_in[2];
    const int*   mask = (const int*)d_in[3];

    float* Out  = (float*)d_out;
    float* Attn = Out + (size_t)BHn * Sn * Dn;

    cudaFuncSetAttribute(attn_hmma, cudaFuncAttributeMaxDynamicSharedMemorySize, SMEM_BYTES);

    dim3 grid(Sn / MQ, BHn);
    attn_hmma<<<grid, NT, SMEM_BYTES>>>(Q, K, V, mask, Out, Attn);
}

// round 11
// speedup vs baseline: 1.0111x; 1.0111x over previous
#include <cuda_runtime.h>
#include <cuda_fp16.h>
#include <cstdint>

// ---------------- problem shape ----------------
#define Bn 4
#define Hn 16
#define Sn 2048
#define Dn 64
#define BHn (Bn*Hn)
#define MQ 128            // queries per CTA
#define TN 128            // keys per smem tile
#define NTILES (Sn/TN)    // 16
#define NT 128            // threads, 4 warps; each warp owns 2 m-blocks

// ---------------- smem layout (bytes) ----------------
#define SM_QH   0
#define SM_KH   16384
#define SM_VH   32768
#define SM_BIAS 49152     // 2048 floats: 0 or -1e30
#define SM_RS   57344
#define SM_INV  57856
#define SM_STG  58368     // per-warp staging: 4 warps x 8 rows x 272B
#define RSTR    68        // floats per staging row (64 + 4 pad)
#define STG_WARP (8*272)  // 2176 bytes per warp
#define SMEM_BYTES (SM_STG + 4*STG_WARP)   // 67072 ; x3 CTAs = 201216 <= 228KB/SM

__device__ __forceinline__ uint32_t swz(uint32_t o) { return o ^ ((o >> 3) & 0x70); }

__device__ __forceinline__ uint32_t s2u(const void* p) {
    uint32_t a;
    asm("{ .reg .u64 t; cvta.to.shared.u64 t, %1; cvt.u32.u64 %0, t; }" : "=r"(a) : "l"(p));
    return a;
}
__device__ __forceinline__ uint32_t ph2(float a, float b) {
    __half2 h = __floats2half2_rn(a, b);
    return *reinterpret_cast<uint32_t*>(&h);
}
__device__ __forceinline__ void ldsm4(uint32_t* r, uint32_t a) {
    asm volatile("ldmatrix.sync.aligned.m8n8.x4.shared.b16 {%0,%1,%2,%3}, [%4];"
        : "=r"(r[0]), "=r"(r[1]), "=r"(r[2]), "=r"(r[3]) : "r"(a));
}
__device__ __forceinline__ void ldsm4t(uint32_t* r, uint32_t a) {
    asm volatile("ldmatrix.sync.aligned.m8n8.x4.trans.shared.b16 {%0,%1,%2,%3}, [%4];"
        : "=r"(r[0]), "=r"(r[1]), "=r"(r[2]), "=r"(r[3]) : "r"(a));
}
__device__ __forceinline__ void mma16816(float* d, const uint32_t* a, const uint32_t* b) {
    asm volatile("mma.sync.aligned.m16n8k16.row.col.f32.f16.f16.f32 "
        "{%0,%1,%2,%3},{%4,%5,%6,%7},{%8,%9},{%0,%1,%2,%3};"
        : "+f"(d[0]), "+f"(d[1]), "+f"(d[2]), "+f"(d[3])
        : "r"(a[0]), "r"(a[1]), "r"(a[2]), "r"(a[3]), "r"(b[0]), "r"(b[1]));
}

// 128x64 fp32 tile -> fp16 smem, swizzled 128B rows. NT=128 -> 8 iters.
__device__ __forceinline__ void load_tile_h(const float* __restrict__ g, char* hi, int tid) {
    #pragma unroll
    for (int it = 0; it < 8; ++it) {
        int chunk = tid + it * NT;
        int r = chunk >> 3, c8 = chunk & 7;
        const float4* p = (const float4*)(g + r * Dn + c8 * 8);
        float4 f0 = p[0], f1 = p[1];
        uint4 hv;
        hv.x = ph2(f0.x, f0.y); hv.y = ph2(f0.z, f0.w);
        hv.z = ph2(f1.x, f1.y); hv.w = ph2(f1.z, f1.w);
        *(uint4*)(hi + swz((uint32_t)(r * 128 + c8 * 16))) = hv;
    }
}

__global__ __launch_bounds__(NT, 3)
void attn_hmma(const float* __restrict__ Q, const float* __restrict__ K,
               const float* __restrict__ V, const int* __restrict__ Mk,
               float* __restrict__ Out, float* __restrict__ Attn)
{
    extern __shared__ char smem[];
    const uint32_t su = s2u(smem);
    const int tid = threadIdx.x, w = tid >> 5, lane = tid & 31;
    const int bh = blockIdx.y, b = bh >> 4;
    const int q0 = blockIdx.x * MQ;
    const size_t qbase = ((size_t)bh * Sn + q0) * Dn;

    // mask -> float bias in smem (0 or -1e30)
    float* bias = (float*)(smem + SM_BIAS);
    #pragma unroll
    for (int i = 0; i < Sn / NT; ++i) {
        int idx = tid + i * NT;
        bias[idx] = Mk[(size_t)b * Sn + idx] ? 0.f : -1e30f;
    }

    // Q tile -> smem (persists across both passes)
    load_tile_h(Q + qbase, smem + SM_QH, tid);
    __syncthreads();

    // per-mb "virtual warp" row: mb=0 -> w, mb=1 -> w+4
    const uint32_t qcs = ((lane >> 4) & 1) * 16;
    const int krb = (lane & 7) + ((lane >> 4) & 1) * 8;
    const uint32_t kcs = ((lane >> 3) & 1) * 16;
    const int cb0 = (lane & 3) * 2;
    int qr[2];
    qr[0] = w * 16 + (lane & 7) + ((lane >> 3) & 1) * 8;
    qr[1] = qr[0] + 64;

    // ============ Pass 1: row sums; Q frags hoisted, K shared over mb ============
    {
        uint32_t qf[2][4][4];
        #pragma unroll
        for (int mb = 0; mb < 2; ++mb)
            #pragma unroll
            for (int ks = 0; ks < 4; ++ks)
                ldsm4(qf[mb][ks], su + SM_QH + swz((uint32_t)(qr[mb] * 128 + ks * 32) + qcs));

        float rs[2][2] = {{0.f, 0.f}, {0.f, 0.f}};
        for (int t = 0; t < NTILES; ++t) {
            if (t) __syncthreads();
            load_tile_h(K + ((size_t)bh * Sn + t * TN) * Dn, smem + SM_KH, tid);
            __syncthreads();
            #pragma unroll
            for (int c = 0; c < 2; ++c) {
                float c_[2][8][4];
                #pragma unroll
                for (int mb = 0; mb < 2; ++mb)
                    #pragma unroll
                    for (int nt = 0; nt < 8; ++nt)
                        #pragma unroll
                        for (int i = 0; i < 4; ++i) c_[mb][nt][i] = 0.f;
                #pragma unroll
                for (int ks = 0; ks < 4; ++ks) {
                    #pragma unroll
                    for (int pr = 0; pr < 4; ++pr) {
                        uint32_t bh_[4];
                        ldsm4(bh_, su + SM_KH + swz((uint32_t)((c * 64 + pr * 16 + krb) * 128 + ks * 32) + kcs));
                        #pragma unroll
                        for (int mb = 0; mb < 2; ++mb) {
                            mma16816(c_[mb][2 * pr],     qf[mb][ks], bh_);
                            mma16816(c_[mb][2 * pr + 1], qf[mb][ks], bh_ + 2);
                        }
                    }
                }
                const float* bp = bias + t * TN + c * 64 + cb0;
                #pragma unroll
                for (int nt = 0; nt < 8; ++nt) {
                    float2 bb = *(const float2*)(bp + nt * 8);
                    #pragma unroll
                    for (int mb = 0; mb < 2; ++mb) {
                        rs[mb][0] += __expf(fmaf(c_[mb][nt][0], 0.125f, bb.x)) + __expf(fmaf(c_[mb][nt][1], 0.125f, bb.y));
                        rs[mb][1] += __expf(fmaf(c_[mb][nt][2], 0.125f, bb.x)) + __expf(fmaf(c_[mb][nt][3], 0.125f, bb.y));
                    }
                }
            }
        }
        #pragma unroll
        for (int mb = 0; mb < 2; ++mb)
            #pragma unroll
            for (int h = 0; h < 2; ++h) {
                rs[mb][h] += __shfl_xor_sync(~0u, rs[mb][h], 1);
                rs[mb][h] += __shfl_xor_sync(~0u, rs[mb][h], 2);
            }
        float* rsm = (float*)(smem + SM_RS);
        if ((lane & 3) == 0) {
            #pragma unroll
            for (int mb = 0; mb < 2; ++mb) {
                int r = (w + 4 * mb) * 16 + (lane >> 2);
                rsm[r]     = rs[mb][0];
                rsm[r + 8] = rs[mb][1];
            }
        }
    }
    __syncthreads();
    {
        float* rsm = (float*)(smem + SM_RS);
        float* invm = (float*)(smem + SM_INV);
        invm[tid] = 1.0f / rsm[tid];
    }
    __syncthreads();
    float inv_[2][2];
    {
        const float* invm = (const float*)(smem + SM_INV);
        #pragma unroll
        for (int mb = 0; mb < 2; ++mb) {
            inv_[mb][0] = invm[(w + 4 * mb) * 16 + (lane >> 2)];
            inv_[mb][1] = invm[(w + 4 * mb) * 16 + 8 + (lane >> 2)];
        }
    }

    // ============ Pass 2: QK, warp-staged attn bulk-copy, PV ============
    float O[2][8][4];
    #pragma unroll
    for (int mb = 0; mb < 2; ++mb)
        #pragma unroll
        for (int j = 0; j < 8; ++j)
            #pragma unroll
            for (int i = 0; i < 4; ++i) O[mb][j][i] = 0.f;

    const int vrb = (lane & 7) + ((lane >> 3) & 1) * 8;
    const uint32_t vcs = ((lane >> 4) & 1) * 16;
    float* stgw = (float*)(smem + SM_STG + w * STG_WARP);     // this warp's 8 rows
    const uint32_t stgu = su + SM_STG + w * STG_WARP;
    float* const attn_base = Attn + ((size_t)bh * Sn) * Sn;

    for (int t = 0; t < NTILES; ++t) {
        __syncthreads();
        load_tile_h(K + ((size_t)bh * Sn + t * TN) * Dn, smem + SM_KH, tid);
        load_tile_h(V + ((size_t)bh * Sn + t * TN) * Dn, smem + SM_VH, tid);
        __syncthreads();
        #pragma unroll
        for (int c = 0; c < 2; ++c) {
            float c_[2][8][4];
            #pragma unroll
            for (int mb = 0; mb < 2; ++mb)
                #pragma unroll
                for (int nt = 0; nt < 8; ++nt)
                    #pragma unroll
                    for (int i = 0; i < 4; ++i) c_[mb][nt][i] = 0.f;
            #pragma unroll
            for (int ks = 0; ks < 4; ++ks) {
                uint32_t ah[2][4];
                #pragma unroll
                for (int mb = 0; mb < 2; ++mb)
                    ldsm4(ah[mb], su + SM_QH + swz((uint32_t)(qr[mb] * 128 + ks * 32) + qcs));
                #pragma unroll
                for (int pr = 0; pr < 4; ++pr) {
                    uint32_t bh_[4];
                    ldsm4(bh_, su + SM_KH + swz((uint32_t)((c * 64 + pr * 16 + krb) * 128 + ks * 32) + kcs));
                    #pragma unroll
                    for (int mb = 0; mb < 2; ++mb) {
                        mma16816(c_[mb][2 * pr],     ah[mb], bh_);
                        mma16816(c_[mb][2 * pr + 1], ah[mb], bh_ + 2);
                    }
                }
            }
            // epilogue: 4 warp-local stages (mb x h): stage 8 rows, bulk-copy to attn
            uint32_t PH[2][8][2];
            const float* bp = bias + t * TN + c * 64 + cb0;
            #pragma unroll
            for (int mb = 0; mb < 2; ++mb) {
                #pragma unroll
                for (int h = 0; h < 2; ++h) {
                    // buffer row r reused only after lane r's previous copy has read it
                    if (lane < 8)
                        asm volatile("cp.async.bulk.wait_group.read 0;" ::: "memory");
                    __syncwarp();
                    #pragma unroll
                    for (int nt = 0; nt < 8; ++nt) {
                        float2 bb = *(const float2*)(bp + nt * 8);
                        float pa = __expf(fmaf(c_[mb][nt][2 * h],     0.125f, bb.x)) * inv_[mb][h];
                        float pb = __expf(fmaf(c_[mb][nt][2 * h + 1], 0.125f, bb.y)) * inv_[mb][h];
                        *(float2*)&stgw[(lane >> 2) * RSTR + nt * 8 + cb0] = make_float2(pa, pb);
                        PH[mb][nt][h] = ph2(pa, pb);
                    }
                    __syncwarp();
                    if (lane < 8) {
                        asm volatile("fence.proxy.async.shared::cta;" ::: "memory");
                        float* dst = attn_base
                                   + ((size_t)(q0 + (w + 4 * mb) * 16 + h * 8 + lane)) * Sn
                                   + t * TN + c * 64;
                        uint32_t src = stgu + (uint32_t)lane * (RSTR * 4);
                        asm volatile("cp.async.bulk.global.shared::cta.bulk_group [%0], [%1], 256;"
                                     :: "l"(dst), "r"(src) : "memory");
                        asm volatile("cp.async.bulk.commit_group;" ::: "memory");
                    }
                }
            }
            // PV: V fragments loaded once, consumed by both m-blocks
            #pragma unroll
            for (int kp = 0; kp < 4; ++kp) {
                uint32_t pah[2][4];
                #pragma unroll
                for (int mb = 0; mb < 2; ++mb) {
                    pah[mb][0] = PH[mb][2*kp][0];   pah[mb][1] = PH[mb][2*kp][1];
                    pah[mb][2] = PH[mb][2*kp+1][0]; pah[mb][3] = PH[mb][2*kp+1][1];
                }
                int vrow = c * 64 + kp * 16 + vrb;
                #pragma unroll
                for (int dp = 0; dp < 4; ++dp) {
                    uint32_t vo = swz((uint32_t)(vrow * 128 + dp * 32) + vcs);
                    uint32_t vb[4];
                    ldsm4t(vb, su + SM_VH + vo);
                    #pragma unroll
                    for (int mb = 0; mb < 2; ++mb) {
                        mma16816(O[mb][2 * dp],     pah[mb], vb);
                        mma16816(O[mb][2 * dp + 1], pah[mb], vb + 2);
                    }
                }
            }
        }
    }

    // ============ O writeback (overlaps tail copies) ============
    #pragma unroll
    for (int mb = 0; mb < 2; ++mb) {
        float* orow0 = Out + ((size_t)bh * Sn + q0 + (w + 4 * mb) * 16 + (lane >> 2)) * Dn;
        float* orow1 = orow0 + 8 * Dn;
        #pragma unroll
        for (int dt = 0; dt < 8; ++dt) {
            int col = dt * 8 + cb0;
            *(float2*)(orow0 + col) = make_float2(O[mb][dt][0], O[mb][dt][1]);
            *(float2*)(orow1 + col) = make_float2(O[mb][dt][2], O[mb][dt][3]);
        }
    }

    // drain outstanding bulk copies before exit
    if (lane < 8)
        asm volatile("cp.async.bulk.wait_group 0;" ::: "memory");
}

extern "C" void kernel_launch(void* const* d_in, const int* in_sizes, int n_in,
                              void* d_out, int out_size)
{
    const float* Q    = (const float*)d_in[0];
    const float* K    = (const float*)d_in[1];
    const float* V    = (const float*)d_in[2];
    const int*   mask = (const int*)d_in[3];

    float* Out  = (float*)d_out;
    float* Attn = Out + (size_t)BHn * Sn * Dn;

    cudaFuncSetAttribute(attn_hmma, cudaFuncAttributeMaxDynamicSharedMemorySize, SMEM_BYTES);

    dim3 grid(Sn / MQ, BHn);
    attn_hmma<<<grid, NT, SMEM_BYTES>>>(Q, K, V, mask, Out, Attn);
}

// round 12
// speedup vs baseline: 1.5756x; 1.5583x over previous
#include <cuda_runtime.h>
#include <cuda_fp16.h>
#include <cstdint>

// ---------------- problem shape ----------------
#define Bn 4
#define Hn 16
#define Sn 2048
#define Dn 64
#define BHn (Bn*Hn)
#define MQ 128            // queries per CTA
#define TN 64             // keys per smem tile
#define NTILES (Sn/TN)    // 32
#define NT 128            // threads, 4 warps; each warp owns 2 m-blocks

// ---------------- fp16 scratch (prep-kernel output) ----------------
__device__ __half QH_g[(size_t)BHn * Sn * Dn];
__device__ __half KH_g[(size_t)BHn * Sn * Dn];
__device__ __half VH_g[(size_t)BHn * Sn * Dn];
__device__ float  BIAS_g[Bn * Sn];

// ---------------- smem layout (bytes) ----------------
#define SM_QH   0          // 128 x 128B
#define SM_KH   16384      // 2 x (64 x 128B)
#define SM_VH   32768      // 2 x (64 x 128B)
#define SM_BIAS 49152      // 2048 floats
#define SM_RS   57344
#define SM_INV  57856
#define SMEM_BYTES 58368   // x3 CTAs = 175104 <= 228KB/SM

__device__ __forceinline__ uint32_t swz(uint32_t o) { return o ^ ((o >> 3) & 0x70); }

__device__ __forceinline__ uint32_t s2u(const void* p) {
    uint32_t a;
    asm("{ .reg .u64 t; cvta.to.shared.u64 t, %1; cvt.u32.u64 %0, t; }" : "=r"(a) : "l"(p));
    return a;
}
__device__ __forceinline__ uint32_t ph2(float a, float b) {
    __half2 h = __floats2half2_rn(a, b);
    return *reinterpret_cast<uint32_t*>(&h);
}
__device__ __forceinline__ void ldsm4(uint32_t* r, uint32_t a) {
    asm volatile("ldmatrix.sync.aligned.m8n8.x4.shared.b16 {%0,%1,%2,%3}, [%4];"
        : "=r"(r[0]), "=r"(r[1]), "=r"(r[2]), "=r"(r[3]) : "r"(a));
}
__device__ __forceinline__ void ldsm4t(uint32_t* r, uint32_t a) {
    asm volatile("ldmatrix.sync.aligned.m8n8.x4.trans.shared.b16 {%0,%1,%2,%3}, [%4];"
        : "=r"(r[0]), "=r"(r[1]), "=r"(r[2]), "=r"(r[3]) : "r"(a));
}
__device__ __forceinline__ void mma16816(float* d, const uint32_t* a, const uint32_t* b) {
    asm volatile("mma.sync.aligned.m16n8k16.row.col.f32.f16.f16.f32 "
        "{%0,%1,%2,%3},{%4,%5,%6,%7},{%8,%9},{%0,%1,%2,%3};"
        : "+f"(d[0]), "+f"(d[1]), "+f"(d[2]), "+f"(d[3])
        : "r"(a[0]), "r"(a[1]), "r"(a[2]), "r"(a[3]), "r"(b[0]), "r"(b[1]));
}
__device__ __forceinline__ void cpa16(uint32_t dst, const void* src) {
    asm volatile("cp.async.ca.shared.global [%0], [%1], 16;" :: "r"(dst), "l"(src));
}
#define CPA_COMMIT() asm volatile("cp.async.commit_group;" ::: "memory")
#define CPA_WAIT0()  asm volatile("cp.async.wait_group 0;" ::: "memory")

// issue one 64-row fp16 tile (8KB) into swizzled smem buffer via cp.async
__device__ __forceinline__ void issue_tile(uint32_t bufbase, const __half* __restrict__ g, int tid) {
    #pragma unroll
    for (int it = 0; it < 4; ++it) {
        int ch = tid + it * NT;
        int r = ch >> 3, c8 = ch & 7;
        cpa16(bufbase + swz((uint32_t)(r * 128 + c8 * 16)), g + r * Dn + c8 * 8);
    }
}

// ---------------- prep kernels ----------------
__global__ void prep_cvt(const float4* __restrict__ Qs, const float4* __restrict__ Ks,
                         const float4* __restrict__ Vs) {
    const size_t n1 = (size_t)BHn * Sn * Dn / 8;   // uint4 (8 halves) chunks per tensor
    size_t i = (size_t)blockIdx.x * blockDim.x + threadIdx.x;
    size_t tsel = i / n1, off = i - tsel * n1;
    const float4* src = tsel == 0 ? Qs : (tsel == 1 ? Ks : Vs);
    __half* dst = tsel == 0 ? QH_g : (tsel == 1 ? KH_g : VH_g);
    float4 a = src[off * 2], b = src[off * 2 + 1];
    uint4 o;
    o.x = ph2(a.x, a.y); o.y = ph2(a.z, a.w);
    o.z = ph2(b.x, b.y); o.w = ph2(b.z, b.w);
    reinterpret_cast<uint4*>(dst)[off] = o;
}
__global__ void prep_bias(const int* __restrict__ Mk) {
    int i = blockIdx.x * blockDim.x + threadIdx.x;
    if (i < Bn * Sn) BIAS_g[i] = Mk[i] ? 0.f : -1e30f;
}

// ---------------- main kernel ----------------
__global__ __launch_bounds__(NT, 3)
void attn_hmma(float* __restrict__ Out, float* __restrict__ Attn)
{
    extern __shared__ char smem[];
    const uint32_t su = s2u(smem);
    const int tid = threadIdx.x, w = tid >> 5, lane = tid & 31;
    const int bh = blockIdx.y, b = bh >> 4;
    const int q0 = blockIdx.x * MQ;

    const __half* Kg = KH_g + (size_t)bh * Sn * Dn;
    const __half* Vg = VH_g + (size_t)bh * Sn * Dn;

    // group 0: Q tile (16KB) + bias (8KB)
    {
        const __half* qg = QH_g + ((size_t)bh * Sn + q0) * Dn;
        #pragma unroll
        for (int it = 0; it < 8; ++it) {
            int ch = tid + it * NT;
            int r = ch >> 3, c8 = ch & 7;
            cpa16(su + SM_QH + swz((uint32_t)(r * 128 + c8 * 16)), qg + r * Dn + c8 * 8);
        }
        const float* bg = BIAS_g + b * Sn;
        #pragma unroll
        for (int it = 0; it < 4; ++it) {
            int ch = tid + it * NT;
            cpa16(su + SM_BIAS + (uint32_t)ch * 16, bg + ch * 4);
        }
        CPA_COMMIT();
    }
    // group 1: K tile 0
    issue_tile(su + SM_KH, Kg, tid);
    CPA_COMMIT();
    CPA_WAIT0();
    __syncthreads();

    const float* bias = (const float*)(smem + SM_BIAS);
    const uint32_t qcs = ((lane >> 4) & 1) * 16;
    const int krb = (lane & 7) + ((lane >> 4) & 1) * 8;
    const uint32_t kcs = ((lane >> 3) & 1) * 16;
    const int cb0 = (lane & 3) * 2;
    int qr[2];
    qr[0] = w * 16 + (lane & 7) + ((lane >> 3) & 1) * 8;
    qr[1] = qr[0] + 64;

    // ============ Pass 1: row sums; Q frags hoisted, K shared over mb ============
    {
        uint32_t qf[2][4][4];
        #pragma unroll
        for (int mb = 0; mb < 2; ++mb)
            #pragma unroll
            for (int ks = 0; ks < 4; ++ks)
                ldsm4(qf[mb][ks], su + SM_QH + swz((uint32_t)(qr[mb] * 128 + ks * 32) + qcs));

        float rs[2][2] = {{0.f, 0.f}, {0.f, 0.f}};
        for (int t = 0; t < NTILES; ++t) {
            if (t + 1 < NTILES) {      // prefetch next K tile into alternate buffer
                issue_tile(su + SM_KH + ((t + 1) & 1) * 8192, Kg + (size_t)(t + 1) * TN * Dn, tid);
                CPA_COMMIT();
            }
            const uint32_t kbuf = su + SM_KH + (t & 1) * 8192;
            float c_[2][8][4];
            #pragma unroll
            for (int mb = 0; mb < 2; ++mb)
                #pragma unroll
                for (int nt = 0; nt < 8; ++nt)
                    #pragma unroll
                    for (int i = 0; i < 4; ++i) c_[mb][nt][i] = 0.f;
            #pragma unroll
            for (int ks = 0; ks < 4; ++ks) {
                #pragma unroll
                for (int pr = 0; pr < 4; ++pr) {
                    uint32_t bh_[4];
                    ldsm4(bh_, kbuf + swz((uint32_t)((pr * 16 + krb) * 128 + ks * 32) + kcs));
                    #pragma unroll
                    for (int mb = 0; mb < 2; ++mb) {
                        mma16816(c_[mb][2 * pr],     qf[mb][ks], bh_);
                        mma16816(c_[mb][2 * pr + 1], qf[mb][ks], bh_ + 2);
                    }
                }
            }
            const float* bp = bias + t * TN + cb0;
            #pragma unroll
            for (int nt = 0; nt < 8; ++nt) {
                float2 bb = *(const float2*)(bp + nt * 8);
                #pragma unroll
                for (int mb = 0; mb < 2; ++mb) {
                    rs[mb][0] += __expf(fmaf(c_[mb][nt][0], 0.125f, bb.x)) + __expf(fmaf(c_[mb][nt][1], 0.125f, bb.y));
                    rs[mb][1] += __expf(fmaf(c_[mb][nt][2], 0.125f, bb.x)) + __expf(fmaf(c_[mb][nt][3], 0.125f, bb.y));
                }
            }
            if (t + 1 < NTILES) { CPA_WAIT0(); __syncthreads(); }
        }
        #pragma unroll
        for (int mb = 0; mb < 2; ++mb)
            #pragma unroll
            for (int h = 0; h < 2; ++h) {
                rs[mb][h] += __shfl_xor_sync(~0u, rs[mb][h], 1);
                rs[mb][h] += __shfl_xor_sync(~0u, rs[mb][h], 2);
            }
        float* rsm = (float*)(smem + SM_RS);
        if ((lane & 3) == 0) {
            #pragma unroll
            for (int mb = 0; mb < 2; ++mb) {
                int r = (w + 4 * mb) * 16 + (lane >> 2);
                rsm[r]     = rs[mb][0];
                rsm[r + 8] = rs[mb][1];
            }
        }
    }
    __syncthreads();
    {
        float* rsm = (float*)(smem + SM_RS);
        float* invm = (float*)(smem + SM_INV);
        invm[tid] = 1.0f / rsm[tid];
    }
    __syncthreads();
    float inv_[2][2];
    {
        const float* invm = (const float*)(smem + SM_INV);
        #pragma unroll
        for (int mb = 0; mb < 2; ++mb) {
            inv_[mb][0] = invm[(w + 4 * mb) * 16 + (lane >> 2)];
            inv_[mb][1] = invm[(w + 4 * mb) * 16 + 8 + (lane >> 2)];
        }
    }

    // ============ Pass 2: QK, attn STG, PV; K+V double-buffered cp.async ============
    float O[2][8][4];
    #pragma unroll
    for (int mb = 0; mb < 2; ++mb)
        #pragma unroll
        for (int j = 0; j < 8; ++j)
            #pragma unroll
            for (int i = 0; i < 4; ++i) O[mb][j][i] = 0.f;

    const int vrb = (lane & 7) + ((lane >> 3) & 1) * 8;
    const uint32_t vcs = ((lane >> 4) & 1) * 16;
    float* ar[2][2];
    #pragma unroll
    for (int mb = 0; mb < 2; ++mb) {
        ar[mb][0] = Attn + ((size_t)bh * Sn + q0 + (w + 4 * mb) * 16 + (lane >> 2)) * Sn;
        ar[mb][1] = ar[mb][0] + (size_t)8 * Sn;
    }

    // prologue: K0+V0 as one group
    issue_tile(su + SM_KH, Kg, tid);
    issue_tile(su + SM_VH, Vg, tid);
    CPA_COMMIT();
    CPA_WAIT0();
    __syncthreads();

    for (int t = 0; t < NTILES; ++t) {
        if (t + 1 < NTILES) {
            issue_tile(su + SM_KH + ((t + 1) & 1) * 8192, Kg + (size_t)(t + 1) * TN * Dn, tid);
            issue_tile(su + SM_VH + ((t + 1) & 1) * 8192, Vg + (size_t)(t + 1) * TN * Dn, tid);
            CPA_COMMIT();
        }
        const uint32_t kbuf = su + SM_KH + (t & 1) * 8192;
        const uint32_t vbuf = su + SM_VH + (t & 1) * 8192;

        float c_[2][8][4];
        #pragma unroll
        for (int mb = 0; mb < 2; ++mb)
            #pragma unroll
            for (int nt = 0; nt < 8; ++nt)
                #pragma unroll
                for (int i = 0; i < 4; ++i) c_[mb][nt][i] = 0.f;
        #pragma unroll
        for (int ks = 0; ks < 4; ++ks) {
            uint32_t ah[2][4];
            #pragma unroll
            for (int mb = 0; mb < 2; ++mb)
                ldsm4(ah[mb], su + SM_QH + swz((uint32_t)(qr[mb] * 128 + ks * 32) + qcs));
            #pragma unroll
            for (int pr = 0; pr < 4; ++pr) {
                uint32_t bh_[4];
                ldsm4(bh_, kbuf + swz((uint32_t)((pr * 16 + krb) * 128 + ks * 32) + kcs));
                #pragma unroll
                for (int mb = 0; mb < 2; ++mb) {
                    mma16816(c_[mb][2 * pr],     ah[mb], bh_);
                    mma16816(c_[mb][2 * pr + 1], ah[mb], bh_ + 2);
                }
            }
        }
        // epilogue: P = exp(s+bias)*inv, attn STG, pack fragments
        uint32_t PH[2][8][2];
        const float* bp = bias + t * TN + cb0;
        #pragma unroll
        for (int mb = 0; mb < 2; ++mb) {
            #pragma unroll
            for (int nt = 0; nt < 8; ++nt) {
                int col = t * TN + nt * 8 + cb0;
                float2 bb = *(const float2*)(bp + nt * 8);
                float p0 = __expf(fmaf(c_[mb][nt][0], 0.125f, bb.x)) * inv_[mb][0];
                float p1 = __expf(fmaf(c_[mb][nt][1], 0.125f, bb.y)) * inv_[mb][0];
                float p2 = __expf(fmaf(c_[mb][nt][2], 0.125f, bb.x)) * inv_[mb][1];
                float p3 = __expf(fmaf(c_[mb][nt][3], 0.125f, bb.y)) * inv_[mb][1];
                *(float2*)(ar[mb][0] + col) = make_float2(p0, p1);
                *(float2*)(ar[mb][1] + col) = make_float2(p2, p3);
                PH[mb][nt][0] = ph2(p0, p1);
                PH[mb][nt][1] = ph2(p2, p3);
            }
        }
        // PV: V fragments loaded once, consumed by both m-blocks
        #pragma unroll
        for (int kp = 0; kp < 4; ++kp) {
            uint32_t pah[2][4];
            #pragma unroll
            for (int mb = 0; mb < 2; ++mb) {
                pah[mb][0] = PH[mb][2*kp][0];   pah[mb][1] = PH[mb][2*kp][1];
                pah[mb][2] = PH[mb][2*kp+1][0]; pah[mb][3] = PH[mb][2*kp+1][1];
            }
            int vrow = kp * 16 + vrb;
            #pragma unroll
            for (int dp = 0; dp < 4; ++dp) {
                uint32_t vb[4];
                ldsm4t(vb, vbuf + swz((uint32_t)(vrow * 128 + dp * 32) + vcs));
                #pragma unroll
                for (int mb = 0; mb < 2; ++mb) {
                    mma16816(O[mb][2 * dp],     pah[mb], vb);
                    mma16816(O[mb][2 * dp + 1], pah[mb], vb + 2);
                }
            }
        }
        if (t + 1 < NTILES) { CPA_WAIT0(); __syncthreads(); }
    }

    // ============ O writeback ============
    #pragma unroll
    for (int mb = 0; mb < 2; ++mb) {
        float* orow0 = Out + ((size_t)bh * Sn + q0 + (w + 4 * mb) * 16 + (lane >> 2)) * Dn;
        float* orow1 = orow0 + 8 * Dn;
        #pragma unroll
        for (int dt = 0; dt < 8; ++dt) {
            int col = dt * 8 + cb0;
            *(float2*)(orow0 + col) = make_float2(O[mb][dt][0], O[mb][dt][1]);
            *(float2*)(orow1 + col) = make_float2(O[mb][dt][2], O[mb][dt][3]);
        }
    }
}

extern "C" void kernel_launch(void* const* d_in, const int* in_sizes, int n_in,
                              void* d_out, int out_size)
{
    const float* Q    = (const float*)d_in[0];
    const float* K    = (const float*)d_in[1];
    const float* V    = (const float*)d_in[2];
    const int*   mask = (const int*)d_in[3];

    float* Out  = (float*)d_out;
    float* Attn = Out + (size_t)BHn * Sn * Dn;

    // prep: fp32 -> fp16 scratch + bias
    const size_t nchunks = (size_t)3 * BHn * Sn * Dn / 8;   // 3145728
    prep_cvt<<<(int)(nchunks / 256), 256>>>((const float4*)Q, (const float4*)K, (const float4*)V);
    prep_bias<<<(Bn * Sn + 255) / 256, 256>>>(mask);

    cudaFuncSetAttribute(attn_hmma, cudaFuncAttributeMaxDynamicSharedMemorySize, SMEM_BYTES);
    dim3 grid(Sn / MQ, BHn);
    attn_hmma<<<grid, NT, SMEM_BYTES>>>(Out, Attn);
}